// round 15
// baseline (speedup 1.0000x reference)
#include <cuda_runtime.h>
#include <cuda_fp16.h>
#include <cstdint>
#include <math.h>

// ---------------- Problem constants ----------------
#define NROWS 16384      // N
#define NMEAS 5120       // n
#define NB    500        // batch
#define NBP   512        // padded batch
#define MSEC  32
#define SIGMA2f 0.2f
#define SCALEf  3.1622776601683795f
#define MAXITR 4

#define BK 64

// gemm_t: CTA 256x128, warp 64x32 (4x4 of 16 warps), 1-term, split-K 16, 512 thr
#define NTHREADS_T 512
#define BM_T 256
#define BN_T 128
#define KSPLIT_T 16
#define KCHUNK_T (NROWS / KSPLIT_T)   // 1024
#define STG_T 4
#define STB_T 49152                   // A 32K | B 16K
#define OFF_BT 32768

// gemm_s: CTA 128x128, warp 64x32 (2x4 of 8 warps), 2-term, split-K 2, 256 thr
#define NTHREADS_S 256
#define BM_S 128
#define BN_S 128
#define KSPLIT_S 2
#define KCHUNK_S (NMEAS / KSPLIT_S)   // 2560
#define STG_S 4
#define STB_S 49152                   // A 16K | Bh 16K | Bl 16K
#define OFF_SB 16384
#define OFF_SBL 32768

#define DYN_SMEM 196608

// ---------------- Scratch (device globals) ----------------
__device__ __half g_A16[(size_t)NMEAS * NROWS];
__device__ __half g_W16[(size_t)NROWS * NMEAS];
__device__ __half g_xTh[(size_t)NBP * NROWS];
__device__ __half g_sTh[(size_t)NBP * NROWS];
__device__ __half g_tTh[(size_t)NBP * NMEAS];
__device__ __half g_tTl[(size_t)NBP * NMEAS];
__device__ float  g_yT[(size_t)NBP * NMEAS];
// partials: gemm_t [16][NBP][NMEAS] = 168MB ; gemm_s [2][NBP][NROWS] = 67MB
__device__ float  g_part[(size_t)KSPLIT_T * NBP * NMEAS];
__device__ double g_taa;
__device__ float  g_colacc[NBP];
__device__ float  g_coef[NBP];

// ---------------- PTX helpers ----------------
__device__ __forceinline__ uint32_t smem_u32(const void* p){
    uint32_t a;
    asm("{ .reg .u64 t; cvta.to.shared.u64 t, %1; cvt.u32.u64 %0, t; }"
        : "=r"(a) : "l"(p));
    return a;
}
__device__ __forceinline__ void cpasync16(uint32_t dst, const void* src){
    asm volatile("cp.async.cg.shared.global [%0], [%1], 16;"
                 :: "r"(dst), "l"(src) : "memory");
}
#define CP_COMMIT()  asm volatile("cp.async.commit_group;" ::: "memory")
#define CP_WAIT(n)   asm volatile("cp.async.wait_group %0;" :: "n"(n) : "memory")

__device__ __forceinline__ void ldsm4(uint32_t& r0, uint32_t& r1, uint32_t& r2,
                                      uint32_t& r3, uint32_t addr){
    asm volatile("ldmatrix.sync.aligned.m8n8.x4.shared.b16 {%0,%1,%2,%3}, [%4];"
                 : "=r"(r0), "=r"(r1), "=r"(r2), "=r"(r3) : "r"(addr));
}
__device__ __forceinline__ void mma16816(float* d, const uint32_t* a, const uint32_t* b){
    asm volatile(
        "mma.sync.aligned.m16n8k16.row.col.f32.f16.f16.f32 "
        "{%0,%1,%2,%3}, {%4,%5,%6,%7}, {%8,%9}, {%0,%1,%2,%3};"
        : "+f"(d[0]), "+f"(d[1]), "+f"(d[2]), "+f"(d[3])
        : "r"(a[0]), "r"(a[1]), "r"(a[2]), "r"(a[3]), "r"(b[0]), "r"(b[1]));
}
__device__ __forceinline__ uint32_t pack_h(__half a, __half b){
    return (uint32_t)__half_as_ushort(a) | ((uint32_t)__half_as_ushort(b) << 16);
}
__device__ __forceinline__ void split_h(float v, __half& hi, __half& lo){
    hi = __float2half_rn(v);
    lo = __float2half_rn(v - __half2float(hi));
}

// ================= gemm_t mainloop: 1-term, warp 64x32, 512 thr ============
__device__ __forceinline__ void gemm_loop_t(
    const __half* __restrict__ Am, const __half* __restrict__ Bm,
    int S, uint32_t smbase, float acc[4][4][4])
{
    const int tid = threadIdx.x, lane = tid & 31, wid = tid >> 5;
    const int wm = wid >> 2, wn = wid & 3;

    // A loader: 256 rows, 2 threads/row, 4 chunks each
    const int arow = tid >> 1;
    const int ac4  = (tid & 1) * 4;
    const int asw  = arow & 7;
    uint32_t ao[4];
    #pragma unroll
    for (int i = 0; i < 4; i++)
        ao[i] = (uint32_t)(arow * 128 + ((ac4 + i) ^ asw) * 16);
    const __half* aP = Am + (size_t)arow * NROWS + ac4 * 8;

    // B loader: 128 rows, 4 threads/row, 2 chunks each
    const int brow = tid >> 2;
    const int bc2  = (tid & 3) * 2;
    const int bsw  = brow & 7;
    const uint32_t bo0 = (uint32_t)(brow * 128 + ((bc2    ) ^ bsw) * 16);
    const uint32_t bo1 = (uint32_t)(brow * 128 + ((bc2 + 1) ^ bsw) * 16);
    const __half* bP = Bm + (size_t)brow * NROWS + bc2 * 8;

    auto issue = [&](int s){
        uint32_t base = smbase + (uint32_t)(s % STG_T) * STB_T;
        const __half* pa = aP + s * BK;
        const __half* pb = bP + s * BK;
        cpasync16(base + ao[0], pa);       cpasync16(base + ao[1], pa + 8);
        cpasync16(base + ao[2], pa + 16);  cpasync16(base + ao[3], pa + 24);
        cpasync16(base + OFF_BT + bo0, pb);  cpasync16(base + OFF_BT + bo1, pb + 8);
    };

    const int rA = wm * 64 + (lane & 15);
    const int swA = rA & 7;
    const int cA = lane >> 4;
    const uint32_t ldA = smbase + rA * 128;
    const int rB = wn * 32 + (lane & 7) + ((lane >> 4) & 1) * 8;
    const int swB = rB & 7;
    const int cBc = (lane >> 3) & 1;
    const uint32_t ldB = smbase + rB * 128;

    #pragma unroll
    for (int p = 0; p < STG_T - 1; p++){
        issue(p);
        CP_COMMIT();
    }

    for (int s = 0; s < S; s++){
        CP_WAIT(STG_T - 2);
        __syncthreads();
        const uint32_t so = (uint32_t)(s % STG_T) * STB_T;
        #pragma unroll
        for (int kk = 0; kk < 4; kk++){
            uint32_t ar[4][4], bh[4][2];
            const uint32_t aoffk = (uint32_t)(((cA + 2 * kk) ^ swA) * 16);
            const uint32_t boffk = (uint32_t)(((cBc + 2 * kk) ^ swB) * 16);
            #pragma unroll
            for (int mf = 0; mf < 4; mf++){
                uint32_t ad = ldA + so + mf * 2048 + aoffk;
                ldsm4(ar[mf][0], ar[mf][1], ar[mf][2], ar[mf][3], ad);
            }
            #pragma unroll
            for (int np = 0; np < 2; np++){
                uint32_t bd = ldB + so + OFF_BT + np * 2048 + boffk;
                ldsm4(bh[np*2][0], bh[np*2][1], bh[np*2+1][0], bh[np*2+1][1], bd);
            }
            #pragma unroll
            for (int mf = 0; mf < 4; mf++)
                #pragma unroll
                for (int nf = 0; nf < 4; nf++)
                    mma16816(acc[mf][nf], ar[mf], bh[nf]);
        }
        int nx = s + STG_T - 1;
        if (nx < S) issue(nx);
        CP_COMMIT();
    }
}

// ================= gemm_s mainloop: 2-term, warp 64x32, 256 thr ============
__device__ __forceinline__ void gemm_loop_s(
    const __half* __restrict__ Am,
    const __half* __restrict__ Bh, const __half* __restrict__ Bl,
    int S, uint32_t smbase, float acc[4][4][4])
{
    const int tid = threadIdx.x, lane = tid & 31, wid = tid >> 5;
    const int wm = wid >> 2, wn = wid & 3;          // 2 x 4 warp grid

    // loaders: each tile 128 rows x 128B; 256 threads -> 2 thr/row, 4 chunks
    const int row = tid >> 1;
    const int c4  = (tid & 1) * 4;
    const int sw  = row & 7;
    uint32_t o[4];
    #pragma unroll
    for (int i = 0; i < 4; i++)
        o[i] = (uint32_t)(row * 128 + ((c4 + i) ^ sw) * 16);
    const int koff = c4 * 8;

    const __half* aP = Am + (size_t)row * NMEAS + koff;
    const __half* bH = Bh + (size_t)row * NMEAS + koff;
    const __half* bL = Bl + (size_t)row * NMEAS + koff;

    auto issue = [&](int s){
        uint32_t base = smbase + (uint32_t)(s % STG_S) * STB_S;
        const __half* pa = aP + s * BK;
        const __half* pb = bH + s * BK;
        const __half* pq = bL + s * BK;
        #pragma unroll
        for (int i = 0; i < 4; i++) cpasync16(base + o[i], pa + i * 8);
        #pragma unroll
        for (int i = 0; i < 4; i++) cpasync16(base + OFF_SB + o[i], pb + i * 8);
        #pragma unroll
        for (int i = 0; i < 4; i++) cpasync16(base + OFF_SBL + o[i], pq + i * 8);
    };

    const int rA = wm * 64 + (lane & 15);
    const int swA = rA & 7;
    const int cA = lane >> 4;
    const uint32_t ldA = smbase + rA * 128;
    const int rB = wn * 32 + (lane & 7) + ((lane >> 4) & 1) * 8;
    const int swB = rB & 7;
    const int cBc = (lane >> 3) & 1;
    const uint32_t ldB = smbase + rB * 128;

    #pragma unroll
    for (int p = 0; p < STG_S - 1; p++){
        issue(p);
        CP_COMMIT();
    }

    for (int s = 0; s < S; s++){
        CP_WAIT(STG_S - 2);
        __syncthreads();
        const uint32_t so = (uint32_t)(s % STG_S) * STB_S;
        #pragma unroll
        for (int kk = 0; kk < 4; kk++){
            uint32_t ar[4][4], bh[4][2], bl[4][2];
            const uint32_t aoffk = (uint32_t)(((cA + 2 * kk) ^ swA) * 16);
            const uint32_t boffk = (uint32_t)(((cBc + 2 * kk) ^ swB) * 16);
            #pragma unroll
            for (int mf = 0; mf < 4; mf++){
                uint32_t ad = ldA + so + mf * 2048 + aoffk;
                ldsm4(ar[mf][0], ar[mf][1], ar[mf][2], ar[mf][3], ad);
            }
            #pragma unroll
            for (int np = 0; np < 2; np++){
                uint32_t bd = ldB + so + OFF_SB + np * 2048 + boffk;
                ldsm4(bh[np*2][0], bh[np*2][1], bh[np*2+1][0], bh[np*2+1][1], bd);
                ldsm4(bl[np*2][0], bl[np*2][1], bl[np*2+1][0], bl[np*2+1][1], bd + 16384);
            }
            #pragma unroll
            for (int mf = 0; mf < 4; mf++)
                #pragma unroll
                for (int nf = 0; nf < 4; nf++)
                    mma16816(acc[mf][nf], ar[mf], bh[nf]);
            #pragma unroll
            for (int mf = 0; mf < 4; mf++)
                #pragma unroll
                for (int nf = 0; nf < 4; nf++)
                    mma16816(acc[mf][nf], ar[mf], bl[nf]);
        }
        int nx = s + STG_S - 1;
        if (nx < S) issue(nx);
        CP_COMMIT();
    }
}

// store acc (warp 64x32 layout) to partial buffer P[col * stride + row]
__device__ __forceinline__ void store_partials64(float acc[4][4][4], float* P,
                                                 int row0, int col0, size_t stride)
{
    const int lane = threadIdx.x & 31, wid = threadIdx.x >> 5;
    const int wm = wid >> 2, wn = wid & 3;
    const int r0 = row0 + wm * 64 + (lane >> 2);
    const int c0 = col0 + wn * 32 + (lane & 3) * 2;
    #pragma unroll
    for (int mf = 0; mf < 4; mf++){
        #pragma unroll
        for (int nf = 0; nf < 4; nf++){
            int r = r0 + mf * 16, cc = c0 + nf * 8;
            P[(size_t)cc * stride + r]           = acc[mf][nf][0];
            P[(size_t)(cc + 1) * stride + r]     = acc[mf][nf][1];
            P[(size_t)cc * stride + r + 8]       = acc[mf][nf][2];
            P[(size_t)(cc + 1) * stride + r + 8] = acc[mf][nf][3];
        }
    }
}

#define ZERO_ACC4(acc)                                        \
    float acc[4][4][4];                                       \
    _Pragma("unroll")                                         \
    for (int i = 0; i < 4; i++)                               \
        _Pragma("unroll")                                     \
        for (int j = 0; j < 4; j++)                           \
            _Pragma("unroll")                                 \
            for (int k = 0; k < 4; k++) acc[i][j][k] = 0.f;

// ---------------- GEMM 1 (split-K 16, 1-term): A @ X partials --------------
__global__ __launch_bounds__(NTHREADS_T, 1)
void gemm_t_split_kernel(int first)
{
    extern __shared__ char sm[];
    const int row0 = blockIdx.x * BM_T, col0 = blockIdx.y * BN_T, z = blockIdx.z;
    const __half* B = (first ? g_xTh : g_sTh) + (size_t)col0 * NROWS + (size_t)z * KCHUNK_T;

    ZERO_ACC4(acc);
    gemm_loop_t(g_A16 + (size_t)row0 * NROWS + (size_t)z * KCHUNK_T,
                B, KCHUNK_T / BK, smem_u32(sm), acc);
    store_partials64(acc, g_part + (size_t)z * NBP * NMEAS, row0, col0, NMEAS);
}

// ------- reduce gemm_t partials + t epilogue + fused colsum(t^2) -----------
__global__ void reduce_t_kernel(const float* __restrict__ noise, int first)
{
    const int c = blockIdx.y;
    const int row = blockIdx.x * 256 + threadIdx.x;
    float a = 0.f;
    #pragma unroll
    for (int z = 0; z < KSPLIT_T; z++)
        a += g_part[((size_t)z * NBP + c) * NMEAS + row];
    float v;
    if (first){
        v = noise[(size_t)row * NB + c] + a;
        g_yT[(size_t)c * NMEAS + row] = v;
    } else {
        v = g_yT[(size_t)c * NMEAS + row] - a;
    }
    __half h, l;
    split_h(v, h, l);
    g_tTh[(size_t)c * NMEAS + row] = h;
    g_tTl[(size_t)c * NMEAS + row] = l;

    float sq = v * v;
    #pragma unroll
    for (int o = 16; o; o >>= 1) sq += __shfl_xor_sync(0xffffffffu, sq, o);
    __shared__ float red[8];
    if ((threadIdx.x & 31) == 0) red[threadIdx.x >> 5] = sq;
    __syncthreads();
    if (threadIdx.x < 8){
        float t = red[threadIdx.x];
        #pragma unroll
        for (int o = 4; o; o >>= 1) t += __shfl_xor_sync(0xffu, t, o);
        if (threadIdx.x == 0) atomicAdd(&g_colacc[c], t);
    }
}

// ---------------- GEMM 2 (split-K 2, 2-term, 256 thr): W @ t partials ------
__global__ __launch_bounds__(NTHREADS_S, 1)
void gemm_s_split_kernel()
{
    extern __shared__ char sm[];
    const int row0 = blockIdx.x * BM_S, col0 = blockIdx.y * BN_S, z = blockIdx.z;

    ZERO_ACC4(acc);
    gemm_loop_s(g_W16 + (size_t)row0 * NMEAS + (size_t)z * KCHUNK_S,
                g_tTh + (size_t)col0 * NMEAS + (size_t)z * KCHUNK_S,
                g_tTl + (size_t)col0 * NMEAS + (size_t)z * KCHUNK_S,
                KCHUNK_S / BK, smem_u32(sm), acc);
    store_partials64(acc, g_part + (size_t)z * NBP * NROWS, row0, col0, NROWS);
}

// -------- reduce gemm_s partials + s-add + coef + section softmax ----------
__global__ void reduce_s_kernel(const float* __restrict__ gammap, int iter,
                                float* __restrict__ outp)
{
    const int col = blockIdx.y;
    const int row = blockIdx.x * 256 + threadIdx.x;
    const float g = gammap[iter];

    float a = g_part[(size_t)col * NROWS + row]
            + g_part[((size_t)NBP + col) * NROWS + row];
    float z = a * g;
    if (iter > 0)
        z += __half2float(g_sTh[(size_t)col * NROWS + row]);
    z *= g_coef[col];

    float m = z;
    #pragma unroll
    for (int o = 16; o; o >>= 1) m = fmaxf(m, __shfl_xor_sync(0xffffffffu, m, o));
    float e = __expf(z - m);
    float su = e;
    #pragma unroll
    for (int o = 16; o; o >>= 1) su += __shfl_xor_sync(0xffffffffu, su, o);
    float v = __fdividef(e, su);

    if (iter == MAXITR - 1){
        outp[(size_t)row * NB + col] = v;
    } else {
        g_sTh[(size_t)col * NROWS + row] = __float2half_rn(v);
    }
}

// ---------------- prep / small kernels --------------------------------------
__global__ void init_scalars_kernel(){
    if (threadIdx.x == 0) g_taa = 0.0;
    if (threadIdx.x < NBP) g_colacc[threadIdx.x] = 0.f;
}

__global__ void conv_f16_kernel(const float* __restrict__ src,
                                __half* __restrict__ dst, long n4, int do_taa)
{
    double t = 0.0;
    const float4* s4 = (const float4*)src;
    uint2* d2 = (uint2*)dst;
    for (long i = (long)blockIdx.x * blockDim.x + threadIdx.x; i < n4;
         i += (long)gridDim.x * blockDim.x){
        float4 v = s4[i];
        d2[i] = make_uint2(pack_h(__float2half_rn(v.x), __float2half_rn(v.y)),
                           pack_h(__float2half_rn(v.z), __float2half_rn(v.w)));
        if (do_taa)
            t += (double)v.x*v.x + (double)v.y*v.y + (double)v.z*v.z + (double)v.w*v.w;
    }
    if (do_taa){
        __shared__ double smd[256];
        smd[threadIdx.x] = t;
        __syncthreads();
        for (int s = 128; s > 0; s >>= 1){
            if (threadIdx.x < s) smd[threadIdx.x] += smd[threadIdx.x + s];
            __syncthreads();
        }
        if (threadIdx.x == 0) atomicAdd(&g_taa, smd[0]);
    }
}

// fused: blocks [0, 2048) convert W ; blocks [2048, 10240) transpose x
#define PREP_CONVW_BLOCKS 2048
#define PREP_TRANS_BLOCKS 8192
__global__ void prep2_kernel(const float* __restrict__ W, const float* __restrict__ x)
{
    if (blockIdx.x < PREP_CONVW_BLOCKS){
        const long n4 = (long)NROWS * NMEAS / 4;
        const float4* s4 = (const float4*)W;
        uint2* d2 = (uint2*)g_W16;
        for (long i = (long)blockIdx.x * 256 + threadIdx.x; i < n4;
             i += (long)PREP_CONVW_BLOCKS * 256){
            float4 v = s4[i];
            d2[i] = make_uint2(pack_h(__float2half_rn(v.x), __float2half_rn(v.y)),
                               pack_h(__float2half_rn(v.z), __float2half_rn(v.w)));
        }
    } else {
        __shared__ float tile[32][33];
        int b = blockIdx.x - PREP_CONVW_BLOCKS;
        int k0 = (b & 511) * 32, n0 = (b >> 9) * 32;
        int tx = threadIdx.x & 31, ty = threadIdx.x >> 5;
        #pragma unroll
        for (int i = 0; i < 32; i += 8){
            int k = k0 + ty + i, n = n0 + tx;
            tile[ty + i][tx] = (n < NB) ? x[(size_t)k * NB + n] : 0.f;
        }
        __syncthreads();
        #pragma unroll
        for (int i = 0; i < 32; i += 8){
            int n = n0 + ty + i, k = k0 + tx;
            g_xTh[(size_t)n * NROWS + k] = __float2half_rn(tile[tx][ty + i]);
        }
    }
}

__global__ void finalize_kernel(const float* __restrict__ gamma, int iter){
    int c = threadIdx.x;
    if (c < NB){
        float taa = (float)g_taa;
        float tww = taa;
        float g = gamma[iter];
        float v2 = (g_colacc[c] - (float)MSEC * SIGMA2f) / taa;
        float tau2 = v2 / (float)NROWS * ((float)NROWS + (g*g - 2.0f*g) * (float)MSEC)
                   + g * g * tww * SIGMA2f / (float)NROWS;
        g_coef[c] = SCALEf / tau2;
    }
    if (c < NBP) g_colacc[c] = 0.f;
}

// ---------------- launch ----------------------------------------------------
extern "C" void kernel_launch(void* const* d_in, const int* in_sizes, int n_in,
                              void* d_out, int out_size)
{
    const float* x     = (const float*)d_in[0];
    const float* noise = (const float*)d_in[2];
    const float* A     = (const float*)d_in[3];
    const float* W     = (const float*)d_in[4];
    const float* gamma = (const float*)d_in[5];
    float* out = (float*)d_out;

    cudaFuncSetAttribute((const void*)gemm_t_split_kernel,
                         cudaFuncAttributeMaxDynamicSharedMemorySize, DYN_SMEM);
    cudaFuncSetAttribute((const void*)gemm_s_split_kernel,
                         cudaFuncAttributeMaxDynamicSharedMemorySize, DYN_SMEM);

    __half *dA16;
    cudaGetSymbolAddress((void**)&dA16, g_A16);

    const long n4 = (long)NMEAS * NROWS / 4;

    // launch order: 4th launch (ncu capture target) = gemm_t_split
    init_scalars_kernel<<<1, 512>>>();                                   // 1
    conv_f16_kernel<<<2048, 256>>>(A, dA16, n4, 1);                      // 2
    prep2_kernel<<<PREP_CONVW_BLOCKS + PREP_TRANS_BLOCKS, 256>>>(W, x);  // 3

    gemm_t_split_kernel<<<dim3(NMEAS/BM_T, NBP/BN_T, KSPLIT_T), NTHREADS_T, DYN_SMEM>>>(1); // 4
    reduce_t_kernel<<<dim3(NMEAS/256, NB), 256>>>(noise, 1);

    for (int it = 0; it < MAXITR; it++){
        finalize_kernel<<<1, 512>>>(gamma, it);
        gemm_s_split_kernel<<<dim3(NROWS/BM_S, NBP/BN_S, KSPLIT_S), NTHREADS_S, DYN_SMEM>>>();
        reduce_s_kernel<<<dim3(NROWS/256, NB), 256>>>(gamma, it, out);
        if (it < MAXITR - 1){
            gemm_t_split_kernel<<<dim3(NMEAS/BM_T, NBP/BN_T, KSPLIT_T), NTHREADS_T, DYN_SMEM>>>(0);
            reduce_t_kernel<<<dim3(NMEAS/256, NB), 256>>>(noise, 0);
        }
    }
}

// round 16
// speedup vs baseline: 1.0762x; 1.0762x over previous
#include <cuda_runtime.h>
#include <cuda_fp16.h>
#include <cstdint>
#include <math.h>

// ---------------- Problem constants ----------------
#define NROWS 16384      // N
#define NMEAS 5120       // n
#define NB    500        // batch
#define NBP   512        // padded batch
#define MSEC  32
#define SIGMA2f 0.2f
#define SCALEf  3.1622776601683795f
#define MAXITR 4

#define NTHREADS 512
#define BK 64

// gemm_t: CTA 256x128, warp 64x32, 1-term, split-K 8
#define BM_T 256
#define BN_T 128
#define KSPLIT_T 8
#define KCHUNK_T (NROWS / KSPLIT_T)   // 2048
#define STG_T 4
#define STB_T 49152                   // A 32K | B 16K
#define OFF_BT 32768

// gemm_s: CTA 128x128, warp 32x32, 2-term, split-K 2  (R14-proven)
#define BM_S 128
#define BN_S 128
#define KSPLIT_S 2
#define KCHUNK_S (NMEAS / KSPLIT_S)   // 2560
#define STG_S 4
#define STB_S 49152                   // A 16K | Bh 16K | Bl 16K
#define OFF_SB 16384
#define OFF_SBL 32768

#define DYN_SMEM 196608

// ---------------- Scratch (device globals) ----------------
__device__ __half g_A16[(size_t)NMEAS * NROWS];
__device__ __half g_W16[(size_t)NROWS * NMEAS];
__device__ __half g_xTh[(size_t)NBP * NROWS];
__device__ __half g_sTh[(size_t)NBP * NROWS];
__device__ __half g_tTh[(size_t)NBP * NMEAS];
__device__ __half g_tTl[(size_t)NBP * NMEAS];
__device__ float  g_yT[(size_t)NBP * NMEAS];
// partials: gemm_t [8][NBP][NMEAS] = 84MB ; gemm_s [2][NBP][NROWS] = 67MB
__device__ float  g_part[(size_t)KSPLIT_T * NBP * NMEAS];
__device__ double g_taa;
__device__ float  g_colacc[NBP];
__device__ float  g_coef[NBP];

// ---------------- PTX helpers ----------------
__device__ __forceinline__ uint32_t smem_u32(const void* p){
    uint32_t a;
    asm("{ .reg .u64 t; cvta.to.shared.u64 t, %1; cvt.u32.u64 %0, t; }"
        : "=r"(a) : "l"(p));
    return a;
}
__device__ __forceinline__ void cpasync16(uint32_t dst, const void* src){
    asm volatile("cp.async.cg.shared.global [%0], [%1], 16;"
                 :: "r"(dst), "l"(src) : "memory");
}
#define CP_COMMIT()  asm volatile("cp.async.commit_group;" ::: "memory")
#define CP_WAIT(n)   asm volatile("cp.async.wait_group %0;" :: "n"(n) : "memory")

__device__ __forceinline__ void ldsm4(uint32_t& r0, uint32_t& r1, uint32_t& r2,
                                      uint32_t& r3, uint32_t addr){
    asm volatile("ldmatrix.sync.aligned.m8n8.x4.shared.b16 {%0,%1,%2,%3}, [%4];"
                 : "=r"(r0), "=r"(r1), "=r"(r2), "=r"(r3) : "r"(addr));
}
__device__ __forceinline__ void mma16816(float* d, const uint32_t* a, const uint32_t* b){
    asm volatile(
        "mma.sync.aligned.m16n8k16.row.col.f32.f16.f16.f32 "
        "{%0,%1,%2,%3}, {%4,%5,%6,%7}, {%8,%9}, {%0,%1,%2,%3};"
        : "+f"(d[0]), "+f"(d[1]), "+f"(d[2]), "+f"(d[3])
        : "r"(a[0]), "r"(a[1]), "r"(a[2]), "r"(a[3]), "r"(b[0]), "r"(b[1]));
}
__device__ __forceinline__ uint32_t pack_h(__half a, __half b){
    return (uint32_t)__half_as_ushort(a) | ((uint32_t)__half_as_ushort(b) << 16);
}
__device__ __forceinline__ void split_h(float v, __half& hi, __half& lo){
    hi = __float2half_rn(v);
    lo = __float2half_rn(v - __half2float(hi));
}

// ================= gemm_t mainloop: 1-term, warp 64x32, CTA 256x128 ========
__device__ __forceinline__ void gemm_loop_t(
    const __half* __restrict__ Am, const __half* __restrict__ Bm,
    int S, uint32_t smbase, float acc[4][4][4])
{
    const int tid = threadIdx.x, lane = tid & 31, wid = tid >> 5;
    const int wm = wid >> 2, wn = wid & 3;

    // A loader: 256 rows, 2 threads/row, 4 chunks each
    const int arow = tid >> 1;
    const int ac4  = (tid & 1) * 4;
    const int asw  = arow & 7;
    uint32_t ao[4];
    #pragma unroll
    for (int i = 0; i < 4; i++)
        ao[i] = (uint32_t)(arow * 128 + ((ac4 + i) ^ asw) * 16);
    const __half* aP = Am + (size_t)arow * NROWS + ac4 * 8;

    // B loader: 128 rows, 4 threads/row, 2 chunks each
    const int brow = tid >> 2;
    const int bc2  = (tid & 3) * 2;
    const int bsw  = brow & 7;
    const uint32_t bo0 = (uint32_t)(brow * 128 + ((bc2    ) ^ bsw) * 16);
    const uint32_t bo1 = (uint32_t)(brow * 128 + ((bc2 + 1) ^ bsw) * 16);
    const __half* bP = Bm + (size_t)brow * NROWS + bc2 * 8;

    auto issue = [&](int s){
        uint32_t base = smbase + (uint32_t)(s % STG_T) * STB_T;
        const __half* pa = aP + s * BK;
        const __half* pb = bP + s * BK;
        cpasync16(base + ao[0], pa);       cpasync16(base + ao[1], pa + 8);
        cpasync16(base + ao[2], pa + 16);  cpasync16(base + ao[3], pa + 24);
        cpasync16(base + OFF_BT + bo0, pb);  cpasync16(base + OFF_BT + bo1, pb + 8);
    };

    const int rA = wm * 64 + (lane & 15);
    const int swA = rA & 7;
    const int cA = lane >> 4;
    const uint32_t ldA = smbase + rA * 128;
    const int rB = wn * 32 + (lane & 7) + ((lane >> 4) & 1) * 8;
    const int swB = rB & 7;
    const int cBc = (lane >> 3) & 1;
    const uint32_t ldB = smbase + rB * 128;

    #pragma unroll
    for (int p = 0; p < STG_T - 1; p++){
        issue(p);
        CP_COMMIT();
    }

    for (int s = 0; s < S; s++){
        CP_WAIT(STG_T - 2);
        __syncthreads();
        const uint32_t so = (uint32_t)(s % STG_T) * STB_T;
        #pragma unroll
        for (int kk = 0; kk < 4; kk++){
            uint32_t ar[4][4], bh[4][2];
            const uint32_t aoffk = (uint32_t)(((cA + 2 * kk) ^ swA) * 16);
            const uint32_t boffk = (uint32_t)(((cBc + 2 * kk) ^ swB) * 16);
            #pragma unroll
            for (int mf = 0; mf < 4; mf++){
                uint32_t ad = ldA + so + mf * 2048 + aoffk;
                ldsm4(ar[mf][0], ar[mf][1], ar[mf][2], ar[mf][3], ad);
            }
            #pragma unroll
            for (int np = 0; np < 2; np++){
                uint32_t bd = ldB + so + OFF_BT + np * 2048 + boffk;
                ldsm4(bh[np*2][0], bh[np*2][1], bh[np*2+1][0], bh[np*2+1][1], bd);
            }
            #pragma unroll
            for (int mf = 0; mf < 4; mf++)
                #pragma unroll
                for (int nf = 0; nf < 4; nf++)
                    mma16816(acc[mf][nf], ar[mf], bh[nf]);
        }
        int nx = s + STG_T - 1;
        if (nx < S) issue(nx);
        CP_COMMIT();
    }
}

// ================= gemm_s mainloop: 2-term, warp 32x32, CTA 128x128 ========
struct FragsS { uint32_t ar[2][4], bh[4][2], bl[4][2]; };

__device__ __forceinline__ void gemm_loop_s(
    const __half* __restrict__ Am,
    const __half* __restrict__ Bh, const __half* __restrict__ Bl,
    int S, uint32_t smbase, float acc[2][4][4])
{
    const int tid = threadIdx.x, lane = tid & 31, wid = tid >> 5;
    const int wm = wid >> 2, wn = wid & 3;

    const int row = tid >> 2;
    const int c2  = (tid & 3) * 2;
    const int sw  = row & 7;
    const uint32_t o0 = (uint32_t)(row * 128 + ((c2    ) ^ sw) * 16);
    const uint32_t o1 = (uint32_t)(row * 128 + ((c2 + 1) ^ sw) * 16);
    const int koff = c2 * 8;

    const __half* aP = Am + (size_t)row * NMEAS + koff;
    const __half* bH = Bh + (size_t)row * NMEAS + koff;
    const __half* bL = Bl + (size_t)row * NMEAS + koff;

    auto issue = [&](int s){
        uint32_t base = smbase + (uint32_t)(s % STG_S) * STB_S;
        const __half* pa = aP + s * BK;
        const __half* pb = bH + s * BK;
        const __half* pq = bL + s * BK;
        cpasync16(base + o0,          pa);  cpasync16(base + o1,          pa + 8);
        cpasync16(base + OFF_SB + o0, pb);  cpasync16(base + OFF_SB + o1, pb + 8);
        cpasync16(base + OFF_SBL + o0, pq); cpasync16(base + OFF_SBL + o1, pq + 8);
    };

    const int rA = wm * 32 + (lane & 15);
    const int swA = rA & 7;
    const int cA = lane >> 4;
    const uint32_t ldA = smbase + rA * 128;
    const int rB = wn * 32 + (lane & 7) + ((lane >> 4) & 1) * 8;
    const int swB = rB & 7;
    const int cBc = (lane >> 3) & 1;
    const uint32_t ldB = smbase + rB * 128;

    auto load_frags = [&](FragsS& f, uint32_t so, int kk){
        const uint32_t aoffk = (uint32_t)(((cA + 2 * kk) ^ swA) * 16);
        const uint32_t boffk = (uint32_t)(((cBc + 2 * kk) ^ swB) * 16);
        #pragma unroll
        for (int mf = 0; mf < 2; mf++){
            uint32_t ad = ldA + so + mf * 2048 + aoffk;
            ldsm4(f.ar[mf][0], f.ar[mf][1], f.ar[mf][2], f.ar[mf][3], ad);
        }
        #pragma unroll
        for (int np = 0; np < 2; np++){
            uint32_t bd = ldB + so + OFF_SB + np * 2048 + boffk;
            ldsm4(f.bh[np*2][0], f.bh[np*2][1], f.bh[np*2+1][0], f.bh[np*2+1][1], bd);
            ldsm4(f.bl[np*2][0], f.bl[np*2][1], f.bl[np*2+1][0], f.bl[np*2+1][1], bd + 16384);
        }
    };
    auto do_mmas = [&](FragsS& f){
        #pragma unroll
        for (int mf = 0; mf < 2; mf++)
            #pragma unroll
            for (int nf = 0; nf < 4; nf++)
                mma16816(acc[mf][nf], f.ar[mf], f.bh[nf]);
        #pragma unroll
        for (int mf = 0; mf < 2; mf++)
            #pragma unroll
            for (int nf = 0; nf < 4; nf++)
                mma16816(acc[mf][nf], f.ar[mf], f.bl[nf]);
    };

    #pragma unroll
    for (int p = 0; p < STG_S - 1; p++){
        issue(p);
        CP_COMMIT();
    }

    FragsS fr[2];
    for (int s = 0; s < S; s++){
        CP_WAIT(STG_S - 2);
        __syncthreads();
        const uint32_t so = (uint32_t)(s % STG_S) * STB_S;
        load_frags(fr[0], so, 0);
        #pragma unroll
        for (int kk = 0; kk < 4; kk++){
            if (kk < 3) load_frags(fr[(kk + 1) & 1], so, kk + 1);
            do_mmas(fr[kk & 1]);
        }
        int nx = s + STG_S - 1;
        if (nx < S) issue(nx);
        CP_COMMIT();
    }
}

// ---------------- GEMM 1 (split-K 8, 1-term): A @ X partials ---------------
__global__ __launch_bounds__(NTHREADS, 1)
void gemm_t_split_kernel(int first)
{
    extern __shared__ char sm[];
    const int row0 = blockIdx.x * BM_T, col0 = blockIdx.y * BN_T, z = blockIdx.z;
    const __half* B = (first ? g_xTh : g_sTh) + (size_t)col0 * NROWS + (size_t)z * KCHUNK_T;

    float acc[4][4][4];
    #pragma unroll
    for (int i = 0; i < 4; i++)
        #pragma unroll
        for (int j = 0; j < 4; j++)
            #pragma unroll
            for (int k = 0; k < 4; k++) acc[i][j][k] = 0.f;

    gemm_loop_t(g_A16 + (size_t)row0 * NROWS + (size_t)z * KCHUNK_T,
                B, KCHUNK_T / BK, smem_u32(sm), acc);

    const int lane = threadIdx.x & 31, wid = threadIdx.x >> 5;
    const int wm = wid >> 2, wn = wid & 3;
    const int r0 = row0 + wm * 64 + (lane >> 2);
    const int c0 = col0 + wn * 32 + (lane & 3) * 2;
    float* P = g_part + (size_t)z * NBP * NMEAS;
    #pragma unroll
    for (int mf = 0; mf < 4; mf++){
        #pragma unroll
        for (int nf = 0; nf < 4; nf++){
            int r = r0 + mf * 16, cc = c0 + nf * 8;
            P[(size_t)cc * NMEAS + r]           = acc[mf][nf][0];
            P[(size_t)(cc + 1) * NMEAS + r]     = acc[mf][nf][1];
            P[(size_t)cc * NMEAS + r + 8]       = acc[mf][nf][2];
            P[(size_t)(cc + 1) * NMEAS + r + 8] = acc[mf][nf][3];
        }
    }
}

// ------- reduce gemm_t partials + t epilogue + fused colsum(t^2) -----------
__global__ void reduce_t_kernel(const float* __restrict__ noise, int first)
{
    const int c = blockIdx.y;
    const int row = blockIdx.x * 256 + threadIdx.x;
    float a = 0.f;
    #pragma unroll
    for (int z = 0; z < KSPLIT_T; z++)
        a += g_part[((size_t)z * NBP + c) * NMEAS + row];
    float v;
    if (first){
        v = noise[(size_t)row * NB + c] + a;
        g_yT[(size_t)c * NMEAS + row] = v;
    } else {
        v = g_yT[(size_t)c * NMEAS + row] - a;
    }
    __half h, l;
    split_h(v, h, l);
    g_tTh[(size_t)c * NMEAS + row] = h;
    g_tTl[(size_t)c * NMEAS + row] = l;

    float sq = v * v;
    #pragma unroll
    for (int o = 16; o; o >>= 1) sq += __shfl_xor_sync(0xffffffffu, sq, o);
    __shared__ float red[8];
    if ((threadIdx.x & 31) == 0) red[threadIdx.x >> 5] = sq;
    __syncthreads();
    if (threadIdx.x < 8){
        float t = red[threadIdx.x];
        #pragma unroll
        for (int o = 4; o; o >>= 1) t += __shfl_xor_sync(0xffu, t, o);
        if (threadIdx.x == 0) atomicAdd(&g_colacc[c], t);
    }
}

// ---------------- GEMM 2 (split-K 2, 2-term): W @ t partials ---------------
__global__ __launch_bounds__(NTHREADS, 1)
void gemm_s_split_kernel()
{
    extern __shared__ char sm[];
    const int row0 = blockIdx.x * BM_S, col0 = blockIdx.y * BN_S, z = blockIdx.z;

    float acc[2][4][4];
    #pragma unroll
    for (int i = 0; i < 2; i++)
        #pragma unroll
        for (int j = 0; j < 4; j++)
            #pragma unroll
            for (int k = 0; k < 4; k++) acc[i][j][k] = 0.f;

    gemm_loop_s(g_W16 + (size_t)row0 * NMEAS + (size_t)z * KCHUNK_S,
                g_tTh + (size_t)col0 * NMEAS + (size_t)z * KCHUNK_S,
                g_tTl + (size_t)col0 * NMEAS + (size_t)z * KCHUNK_S,
                KCHUNK_S / BK, smem_u32(sm), acc);

    const int lane = threadIdx.x & 31, wid = threadIdx.x >> 5;
    const int wm = wid >> 2, wn = wid & 3;
    const int r0 = row0 + wm * 32 + (lane >> 2);
    const int c0 = col0 + wn * 32 + (lane & 3) * 2;
    float* P = g_part + (size_t)z * NBP * NROWS;
    #pragma unroll
    for (int mf = 0; mf < 2; mf++){
        #pragma unroll
        for (int nf = 0; nf < 4; nf++){
            int r = r0 + mf * 16, cc = c0 + nf * 8;
            P[(size_t)cc * NROWS + r]           = acc[mf][nf][0];
            P[(size_t)(cc + 1) * NROWS + r]     = acc[mf][nf][1];
            P[(size_t)cc * NROWS + r + 8]       = acc[mf][nf][2];
            P[(size_t)(cc + 1) * NROWS + r + 8] = acc[mf][nf][3];
        }
    }
}

// -------- reduce gemm_s partials + s-add + coef + section softmax ----------
__global__ void reduce_s_kernel(const float* __restrict__ gammap, int iter,
                                float* __restrict__ outp)
{
    const int col = blockIdx.y;
    const int row = blockIdx.x * 256 + threadIdx.x;
    const float g = gammap[iter];

    float a = g_part[(size_t)col * NROWS + row]
            + g_part[((size_t)NBP + col) * NROWS + row];
    float z = a * g;
    if (iter > 0)
        z += __half2float(g_sTh[(size_t)col * NROWS + row]);
    z *= g_coef[col];

    float m = z;
    #pragma unroll
    for (int o = 16; o; o >>= 1) m = fmaxf(m, __shfl_xor_sync(0xffffffffu, m, o));
    float e = __expf(z - m);
    float su = e;
    #pragma unroll
    for (int o = 16; o; o >>= 1) su += __shfl_xor_sync(0xffffffffu, su, o);
    float v = __fdividef(e, su);

    if (iter == MAXITR - 1){
        outp[(size_t)row * NB + col] = v;
    } else {
        g_sTh[(size_t)col * NROWS + row] = __float2half_rn(v);
    }
}

// ---------------- prep / small kernels --------------------------------------
__global__ void init_scalars_kernel(){
    if (threadIdx.x == 0) g_taa = 0.0;
    if (threadIdx.x < NBP) g_colacc[threadIdx.x] = 0.f;
}

__global__ void conv_f16_kernel(const float* __restrict__ src,
                                __half* __restrict__ dst, long n4, int do_taa)
{
    double t = 0.0;
    const float4* s4 = (const float4*)src;
    uint2* d2 = (uint2*)dst;
    for (long i = (long)blockIdx.x * blockDim.x + threadIdx.x; i < n4;
         i += (long)gridDim.x * blockDim.x){
        float4 v = s4[i];
        d2[i] = make_uint2(pack_h(__float2half_rn(v.x), __float2half_rn(v.y)),
                           pack_h(__float2half_rn(v.z), __float2half_rn(v.w)));
        if (do_taa)
            t += (double)v.x*v.x + (double)v.y*v.y + (double)v.z*v.z + (double)v.w*v.w;
    }
    if (do_taa){
        __shared__ double smd[256];
        smd[threadIdx.x] = t;
        __syncthreads();
        for (int s = 128; s > 0; s >>= 1){
            if (threadIdx.x < s) smd[threadIdx.x] += smd[threadIdx.x + s];
            __syncthreads();
        }
        if (threadIdx.x == 0) atomicAdd(&g_taa, smd[0]);
    }
}

// fused: blocks [0, 2048) convert W ; blocks [2048, 10240) transpose x
#define PREP_CONVW_BLOCKS 2048
#define PREP_TRANS_BLOCKS 8192
__global__ void prep2_kernel(const float* __restrict__ W, const float* __restrict__ x)
{
    if (blockIdx.x < PREP_CONVW_BLOCKS){
        const long n4 = (long)NROWS * NMEAS / 4;
        const float4* s4 = (const float4*)W;
        uint2* d2 = (uint2*)g_W16;
        for (long i = (long)blockIdx.x * 256 + threadIdx.x; i < n4;
             i += (long)PREP_CONVW_BLOCKS * 256){
            float4 v = s4[i];
            d2[i] = make_uint2(pack_h(__float2half_rn(v.x), __float2half_rn(v.y)),
                               pack_h(__float2half_rn(v.z), __float2half_rn(v.w)));
        }
    } else {
        __shared__ float tile[32][33];
        int b = blockIdx.x - PREP_CONVW_BLOCKS;
        int k0 = (b & 511) * 32, n0 = (b >> 9) * 32;
        int tx = threadIdx.x & 31, ty = threadIdx.x >> 5;
        #pragma unroll
        for (int i = 0; i < 32; i += 8){
            int k = k0 + ty + i, n = n0 + tx;
            tile[ty + i][tx] = (n < NB) ? x[(size_t)k * NB + n] : 0.f;
        }
        __syncthreads();
        #pragma unroll
        for (int i = 0; i < 32; i += 8){
            int n = n0 + ty + i, k = k0 + tx;
            g_xTh[(size_t)n * NROWS + k] = __float2half_rn(tile[tx][ty + i]);
        }
    }
}

__global__ void finalize_kernel(const float* __restrict__ gamma, int iter){
    int c = threadIdx.x;
    if (c < NB){
        float taa = (float)g_taa;
        float tww = taa;
        float g = gamma[iter];
        float v2 = (g_colacc[c] - (float)MSEC * SIGMA2f) / taa;
        float tau2 = v2 / (float)NROWS * ((float)NROWS + (g*g - 2.0f*g) * (float)MSEC)
                   + g * g * tww * SIGMA2f / (float)NROWS;
        g_coef[c] = SCALEf / tau2;
    }
    if (c < NBP) g_colacc[c] = 0.f;
}

// ---------------- launch ----------------------------------------------------
extern "C" void kernel_launch(void* const* d_in, const int* in_sizes, int n_in,
                              void* d_out, int out_size)
{
    const float* x     = (const float*)d_in[0];
    const float* noise = (const float*)d_in[2];
    const float* A     = (const float*)d_in[3];
    const float* W     = (const float*)d_in[4];
    const float* gamma = (const float*)d_in[5];
    float* out = (float*)d_out;

    cudaFuncSetAttribute((const void*)gemm_t_split_kernel,
                         cudaFuncAttributeMaxDynamicSharedMemorySize, DYN_SMEM);
    cudaFuncSetAttribute((const void*)gemm_s_split_kernel,
                         cudaFuncAttributeMaxDynamicSharedMemorySize, DYN_SMEM);

    __half *dA16;
    cudaGetSymbolAddress((void**)&dA16, g_A16);

    const long n4 = (long)NMEAS * NROWS / 4;

    // launch order: 4th launch (ncu capture target) = gemm_t_split
    init_scalars_kernel<<<1, 512>>>();                                   // 1
    conv_f16_kernel<<<2048, 256>>>(A, dA16, n4, 1);                      // 2
    prep2_kernel<<<PREP_CONVW_BLOCKS + PREP_TRANS_BLOCKS, 256>>>(W, x);  // 3

    gemm_t_split_kernel<<<dim3(NMEAS/BM_T, NBP/BN_T, KSPLIT_T), NTHREADS, DYN_SMEM>>>(1); // 4
    reduce_t_kernel<<<dim3(NMEAS/256, NB), 256>>>(noise, 1);

    for (int it = 0; it < MAXITR; it++){
        finalize_kernel<<<1, 512>>>(gamma, it);
        gemm_s_split_kernel<<<dim3(NROWS/BM_S, NBP/BN_S, KSPLIT_S), NTHREADS, DYN_SMEM>>>();
        reduce_s_kernel<<<dim3(NROWS/256, NB), 256>>>(gamma, it, out);
        if (it < MAXITR - 1){
            gemm_t_split_kernel<<<dim3(NMEAS/BM_T, NBP/BN_T, KSPLIT_T), NTHREADS, DYN_SMEM>>>(0);
            reduce_t_kernel<<<dim3(NMEAS/256, NB), 256>>>(noise, 0);
        }
    }
}